// round 3
// baseline (speedup 1.0000x reference)
#include <cuda_runtime.h>

// Self-attention (N=2, L=2048, H=16, Dv=64) + FC(1024,1024), fp32 baseline.
// Stage 1: flash-style attention per (n, h, 64-query tile) -> g_attn scratch.
// Stage 2: tiled SGEMM  out = g_attn @ fc_w^T + fc_b.

#define L_SEQ   2048
#define D_MODEL 1024
#define N_HEADS 16
#define D_V     64
#define BM      64
#define BN      64
#define PAD     4
#define TSTR    (BM + PAD)   // 68, row stride for transposed smem tiles

// 2*2048*1024 fp32 scratch for attention output (device global: no allocs).
__device__ float g_attn[2 * L_SEQ * D_MODEL];

__global__ __launch_bounds__(256, 2)
void attn_kernel(const float* __restrict__ Q,
                 const float* __restrict__ K,
                 const float* __restrict__ V,
                 const int*   __restrict__ mask)
{
    const int qtile = blockIdx.x;   // 0..31
    const int h     = blockIdx.y;   // 0..15
    const int n     = blockIdx.z;   // 0..1
    const int tid   = threadIdx.x;
    const int tx    = tid & 15;     // output col group (keys / dv)
    const int ty    = tid >> 4;     // output row group (queries)

    __shared__ float Qt[D_V][TSTR];  // [d][r]  (Q tile, transposed)
    __shared__ float Kt[D_V][TSTR];  // [d][c]  (K tile, transposed)
    __shared__ float Vs[BN][TSTR];   // [c][d]  (V tile, natural)
    __shared__ float Pt[BN][TSTR];   // [c][r]  (P tile, transposed)
    __shared__ int   msk[BN];

    const float* qbase = Q + ((size_t)(n * L_SEQ + qtile * BM) * D_MODEL + h * D_V);
    // Load Q tile [64 x 64], store transposed.
    for (int i = tid; i < BM * 16; i += 256) {
        int r  = i >> 4;
        int c4 = (i & 15) << 2;
        float4 v = *(const float4*)(qbase + (size_t)r * D_MODEL + c4);
        Qt[c4 + 0][r] = v.x; Qt[c4 + 1][r] = v.y;
        Qt[c4 + 2][r] = v.z; Qt[c4 + 3][r] = v.w;
    }

    float acc[4][4];
    #pragma unroll
    for (int i = 0; i < 4; i++)
        #pragma unroll
        for (int j = 0; j < 4; j++) acc[i][j] = 0.f;
    float mrow[4], lrow[4];
    #pragma unroll
    for (int i = 0; i < 4; i++) { mrow[i] = -1e30f; lrow[i] = 0.f; }

    const float* kbase = K + ((size_t)n * L_SEQ * D_MODEL + h * D_V);
    const float* vbase = V + ((size_t)n * L_SEQ * D_MODEL + h * D_V);
    const int*   mbase = mask + n * L_SEQ;

    for (int kb = 0; kb < L_SEQ / BN; kb++) {
        __syncthreads();   // prior-iter readers of Kt/Vs/Pt are done
        const float* kp = kbase + (size_t)kb * BN * D_MODEL;
        const float* vp = vbase + (size_t)kb * BN * D_MODEL;
        for (int i = tid; i < BN * 16; i += 256) {
            int r  = i >> 4;
            int c4 = (i & 15) << 2;
            float4 kv = *(const float4*)(kp + (size_t)r * D_MODEL + c4);
            Kt[c4 + 0][r] = kv.x; Kt[c4 + 1][r] = kv.y;
            Kt[c4 + 2][r] = kv.z; Kt[c4 + 3][r] = kv.w;
            float4 vv = *(const float4*)(vp + (size_t)r * D_MODEL + c4);
            *(float4*)&Vs[r][c4] = vv;
        }
        if (tid < BN) msk[tid] = mbase[kb * BN + tid];
        __syncthreads();

        // S = (Q K^T) / 32, with key-padding mask -> -1e30 (finite sentinel).
        float s[4][4];
        #pragma unroll
        for (int i = 0; i < 4; i++)
            #pragma unroll
            for (int j = 0; j < 4; j++) s[i][j] = 0.f;
        #pragma unroll 8
        for (int kk = 0; kk < D_V; kk++) {
            float4 qv = *(const float4*)&Qt[kk][4 * ty];
            float4 kv = *(const float4*)&Kt[kk][4 * tx];
            float qa[4] = {qv.x, qv.y, qv.z, qv.w};
            float ka[4] = {kv.x, kv.y, kv.z, kv.w};
            #pragma unroll
            for (int i = 0; i < 4; i++)
                #pragma unroll
                for (int j = 0; j < 4; j++) s[i][j] += qa[i] * ka[j];
        }
        int mk[4];
        #pragma unroll
        for (int j = 0; j < 4; j++) mk[j] = msk[4 * tx + j];
        #pragma unroll
        for (int i = 0; i < 4; i++)
            #pragma unroll
            for (int j = 0; j < 4; j++)
                s[i][j] = mk[j] ? s[i][j] * 0.03125f : -1e30f;

        // Online softmax: per-row max/sum reduced across the 16-lane tx group.
        float mnew[4], alpha[4];
        #pragma unroll
        for (int i = 0; i < 4; i++) {
            float v = fmaxf(fmaxf(s[i][0], s[i][1]), fmaxf(s[i][2], s[i][3]));
            #pragma unroll
            for (int off = 8; off >= 1; off >>= 1)
                v = fmaxf(v, __shfl_xor_sync(0xffffffffu, v, off));
            mnew[i]  = fmaxf(mrow[i], v);
            alpha[i] = __expf(mrow[i] - mnew[i]);
        }
        #pragma unroll
        for (int i = 0; i < 4; i++) {
            float sum = 0.f;
            #pragma unroll
            for (int j = 0; j < 4; j++) {
                float p = __expf(s[i][j] - mnew[i]);
                s[i][j] = p;
                sum += p;
            }
            #pragma unroll
            for (int off = 8; off >= 1; off >>= 1)
                sum += __shfl_xor_sync(0xffffffffu, sum, off);
            lrow[i] = lrow[i] * alpha[i] + sum;
            mrow[i] = mnew[i];
        }
        #pragma unroll
        for (int i = 0; i < 4; i++)
            #pragma unroll
            for (int j = 0; j < 4; j++) acc[i][j] *= alpha[i];

        // Stage P transposed, then O += P @ V.
        #pragma unroll
        for (int j = 0; j < 4; j++)
            *(float4*)&Pt[4 * tx + j][4 * ty] =
                make_float4(s[0][j], s[1][j], s[2][j], s[3][j]);
        __syncthreads();
        #pragma unroll 8
        for (int c = 0; c < BN; c++) {
            float4 pv = *(const float4*)&Pt[c][4 * ty];
            float4 vv = *(const float4*)&Vs[c][4 * tx];
            float pa[4] = {pv.x, pv.y, pv.z, pv.w};
            float va[4] = {vv.x, vv.y, vv.z, vv.w};
            #pragma unroll
            for (int i = 0; i < 4; i++)
                #pragma unroll
                for (int j = 0; j < 4; j++) acc[i][j] += pa[i] * va[j];
        }
    }

    // Epilogue: normalize and store to scratch (layout [n, q, h*64 + d]).
    float* obase = g_attn + ((size_t)(n * L_SEQ + qtile * BM) * D_MODEL + h * D_V);
    #pragma unroll
    for (int i = 0; i < 4; i++) {
        float inv = 1.f / lrow[i];
        float4 o = make_float4(acc[i][0] * inv, acc[i][1] * inv,
                               acc[i][2] * inv, acc[i][3] * inv);
        *(float4*)(obase + (size_t)(4 * ty + i) * D_MODEL + 4 * tx) = o;
    }
}

// out[m][o] = sum_k X[m][k] * W[o][k] + b[o];  X = g_attn, M = 4096.
__global__ __launch_bounds__(256, 2)
void fc_kernel(const float* __restrict__ W,
               const float* __restrict__ b,
               float*       __restrict__ out)
{
    const int otile = blockIdx.x;   // 0..15
    const int mtile = blockIdx.y;   // 0..63
    const int tid = threadIdx.x;
    const int tx = tid & 15, ty = tid >> 4;

    __shared__ float Xt[64][TSTR];  // [k][m]
    __shared__ float Wt[64][TSTR];  // [k][o]

    float acc[4][4];
    #pragma unroll
    for (int i = 0; i < 4; i++)
        #pragma unroll
        for (int j = 0; j < 4; j++) acc[i][j] = 0.f;

    for (int kb = 0; kb < D_MODEL / 64; kb++) {
        __syncthreads();
        for (int i = tid; i < 64 * 16; i += 256) {
            int r  = i >> 4;
            int c4 = (i & 15) << 2;
            float4 xv = *(const float4*)(g_attn +
                (size_t)(mtile * 64 + r) * D_MODEL + kb * 64 + c4);
            Xt[c4 + 0][r] = xv.x; Xt[c4 + 1][r] = xv.y;
            Xt[c4 + 2][r] = xv.z; Xt[c4 + 3][r] = xv.w;
            float4 wv = *(const float4*)(W +
                (size_t)(otile * 64 + r) * D_MODEL + kb * 64 + c4);
            Wt[c4 + 0][r] = wv.x; Wt[c4 + 1][r] = wv.y;
            Wt[c4 + 2][r] = wv.z; Wt[c4 + 3][r] = wv.w;
        }
        __syncthreads();
        #pragma unroll 8
        for (int kk = 0; kk < 64; kk++) {
            float4 xv = *(const float4*)&Xt[kk][4 * ty];
            float4 wv = *(const float4*)&Wt[kk][4 * tx];
            float xa[4] = {xv.x, xv.y, xv.z, xv.w};
            float wa[4] = {wv.x, wv.y, wv.z, wv.w};
            #pragma unroll
            for (int i = 0; i < 4; i++)
                #pragma unroll
                for (int j = 0; j < 4; j++) acc[i][j] += xa[i] * wa[j];
        }
    }

    float bj[4];
    #pragma unroll
    for (int j = 0; j < 4; j++) bj[j] = b[otile * 64 + 4 * tx + j];
    #pragma unroll
    for (int i = 0; i < 4; i++) {
        float4 o = make_float4(acc[i][0] + bj[0], acc[i][1] + bj[1],
                               acc[i][2] + bj[2], acc[i][3] + bj[3]);
        *(float4*)(out + (size_t)(mtile * 64 + 4 * ty + i) * D_MODEL
                       + otile * 64 + 4 * tx) = o;
    }
}

extern "C" void kernel_launch(void* const* d_in, const int* in_sizes, int n_in,
                              void* d_out, int out_size)
{
    const float* q    = (const float*)d_in[0];
    const float* k    = (const float*)d_in[1];
    const float* v    = (const float*)d_in[2];
    const int*   mask = (const int*)  d_in[3];
    const float* fw   = (const float*)d_in[4];
    const float* fb   = (const float*)d_in[5];
    float* out = (float*)d_out;

    dim3 g1(L_SEQ / BM, N_HEADS, 2);
    attn_kernel<<<g1, 256>>>(q, k, v, mask);

    dim3 g2(D_MODEL / 64, (2 * L_SEQ) / 64);
    fc_kernel<<<g2, 256>>>(fw, fb, out);
}

// round 5
// speedup vs baseline: 3.1569x; 3.1569x over previous
#include <cuda_runtime.h>
#include <cstdint>

#define L_SEQ 2048
#define DM    1024
#define NH    16
#define DV    64

// attention output scratch [4096,1024] fp32
__device__ float g_attn[2 * L_SEQ * DM];

// ---- helpers ----
__device__ __forceinline__ uint32_t f2tf(float f) {
    uint32_t u;
    asm("cvt.rna.tf32.f32 %0, %1;" : "=r"(u) : "f"(f));
    return u;
}
__device__ __forceinline__ void sts4_tf(uint32_t* p, float4 v) {
    uint4 u = make_uint4(f2tf(v.x), f2tf(v.y), f2tf(v.z), f2tf(v.w));
    *(uint4*)p = u;
}
__device__ __forceinline__ void mma8(float* c, const uint32_t* a,
                                     uint32_t b0, uint32_t b1) {
    asm volatile(
        "mma.sync.aligned.m16n8k8.row.col.f32.tf32.tf32.f32 "
        "{%0,%1,%2,%3}, {%4,%5,%6,%7}, {%8,%9}, {%0,%1,%2,%3};"
        : "+f"(c[0]), "+f"(c[1]), "+f"(c[2]), "+f"(c[3])
        : "r"(a[0]), "r"(a[1]), "r"(a[2]), "r"(a[3]), "r"(b0), "r"(b1));
}

// ================= attention =================
// CTA: 128 thr (4 warps) per (64-query tile, head, batch). Key blocks of 64.
// SMEM (u32 words): Q[64*68] K[64*68] V[64*68] P[64*68] mask[64]
#define SD 68
#define ATT_SMEM ((4 * 64 * SD + 64) * 4)   // 69888 B

__global__ __launch_bounds__(128, 3)
void attn_mma(const float* __restrict__ Q, const float* __restrict__ K,
              const float* __restrict__ V, const int* __restrict__ mask)
{
    extern __shared__ uint32_t sm[];
    uint32_t* sQ = sm;
    uint32_t* sK = sm + 64 * SD;
    uint32_t* sV = sm + 2 * 64 * SD;
    uint32_t* sP = sm + 3 * 64 * SD;
    int*      smk = (int*)(sm + 4 * 64 * SD);

    const int qb = blockIdx.x, hd = blockIdx.y, n = blockIdx.z;
    const int tid = threadIdx.x, w = tid >> 5, lane = tid & 31;
    const int g = lane >> 2, l4 = lane & 3;
    const int rlo = w * 16 + g, rhi = rlo + 8;

    // ---- load Q tile [64 x 64] as tf32 ----
    const float* qp = Q + ((size_t)(n * L_SEQ + qb * 64)) * DM + hd * DV;
    #pragma unroll
    for (int j = 0; j < 8; j++) {
        int idx = tid + j * 128;                 // 1024 float4 slots
        int r = idx >> 4, c4 = (idx & 15) << 2;
        sts4_tf(&sQ[r * SD + c4], *(const float4*)(qp + (size_t)r * DM + c4));
    }
    __syncthreads();

    // ---- preload Q A-fragments (live whole kernel) ----
    uint32_t qa[8][4];
    #pragma unroll
    for (int kt = 0; kt < 8; kt++) {
        qa[kt][0] = sQ[rlo * SD + kt * 8 + l4];
        qa[kt][1] = sQ[rhi * SD + kt * 8 + l4];
        qa[kt][2] = sQ[rlo * SD + kt * 8 + l4 + 4];
        qa[kt][3] = sQ[rhi * SD + kt * 8 + l4 + 4];
    }

    float oc[8][4];
    #pragma unroll
    for (int i = 0; i < 8; i++)
        #pragma unroll
        for (int j = 0; j < 4; j++) oc[i][j] = 0.f;
    float m_lo = -1e30f, m_hi = -1e30f, l_lo = 0.f, l_hi = 0.f;

    const float* kp0 = K + ((size_t)n * L_SEQ) * DM + hd * DV;
    const float* vp0 = V + ((size_t)n * L_SEQ) * DM + hd * DV;
    const int*   mp0 = mask + n * L_SEQ;

    for (int kb = 0; kb < L_SEQ / 64; kb++) {
        __syncthreads();   // previous-iter readers of sK/sV done
        const float* kp = kp0 + (size_t)kb * 64 * DM;
        const float* vp = vp0 + (size_t)kb * 64 * DM;
        #pragma unroll
        for (int j = 0; j < 8; j++) {
            int idx = tid + j * 128;
            int r = idx >> 4, c4 = (idx & 15) << 2;
            sts4_tf(&sK[r * SD + c4], *(const float4*)(kp + (size_t)r * DM + c4));
            sts4_tf(&sV[r * SD + c4], *(const float4*)(vp + (size_t)r * DM + c4));
        }
        if (tid < 64) smk[tid] = mp0[kb * 64 + tid];
        __syncthreads();

        // ---- S = Q K^T : 8 kt x 8 nt mma ----
        float sc[8][4];
        #pragma unroll
        for (int i = 0; i < 8; i++)
            #pragma unroll
            for (int j = 0; j < 4; j++) sc[i][j] = 0.f;
        #pragma unroll
        for (int nt = 0; nt < 8; nt++) {
            const uint32_t* krow0 = &sK[(nt * 8 + g) * SD];
            #pragma unroll
            for (int kt = 0; kt < 8; kt++) {
                uint32_t b0 = krow0[kt * 8 + l4];
                uint32_t b1 = krow0[kt * 8 + l4 + 4];
                mma8(sc[nt], qa[kt], b0, b1);
            }
        }

        // ---- mask + scale, row max ----
        float vlo = -1e30f, vhi = -1e30f;
        #pragma unroll
        for (int nt = 0; nt < 8; nt++) {
            int2 mk = *(const int2*)&smk[nt * 8 + 2 * l4];
            sc[nt][0] = mk.x ? sc[nt][0] * 0.03125f : -1e30f;
            sc[nt][1] = mk.y ? sc[nt][1] * 0.03125f : -1e30f;
            sc[nt][2] = mk.x ? sc[nt][2] * 0.03125f : -1e30f;
            sc[nt][3] = mk.y ? sc[nt][3] * 0.03125f : -1e30f;
            vlo = fmaxf(vlo, fmaxf(sc[nt][0], sc[nt][1]));
            vhi = fmaxf(vhi, fmaxf(sc[nt][2], sc[nt][3]));
        }
        vlo = fmaxf(vlo, __shfl_xor_sync(0xffffffffu, vlo, 1));
        vlo = fmaxf(vlo, __shfl_xor_sync(0xffffffffu, vlo, 2));
        vhi = fmaxf(vhi, __shfl_xor_sync(0xffffffffu, vhi, 1));
        vhi = fmaxf(vhi, __shfl_xor_sync(0xffffffffu, vhi, 2));
        float mn_lo = fmaxf(m_lo, vlo), mn_hi = fmaxf(m_hi, vhi);
        float al_lo = __expf(m_lo - mn_lo), al_hi = __expf(m_hi - mn_hi);
        m_lo = mn_lo; m_hi = mn_hi;

        // ---- exp, P -> smem (tf32), row sums ----
        float slo = 0.f, shi = 0.f;
        #pragma unroll
        for (int nt = 0; nt < 8; nt++) {
            float p0 = __expf(sc[nt][0] - mn_lo);
            float p1 = __expf(sc[nt][1] - mn_lo);
            float p2 = __expf(sc[nt][2] - mn_hi);
            float p3 = __expf(sc[nt][3] - mn_hi);
            slo += p0 + p1; shi += p2 + p3;
            int col = nt * 8 + 2 * l4;
            *(uint2*)&sP[rlo * SD + col] = make_uint2(f2tf(p0), f2tf(p1));
            *(uint2*)&sP[rhi * SD + col] = make_uint2(f2tf(p2), f2tf(p3));
        }
        slo += __shfl_xor_sync(0xffffffffu, slo, 1);
        slo += __shfl_xor_sync(0xffffffffu, slo, 2);
        shi += __shfl_xor_sync(0xffffffffu, shi, 1);
        shi += __shfl_xor_sync(0xffffffffu, shi, 2);
        l_lo = l_lo * al_lo + slo;
        l_hi = l_hi * al_hi + shi;

        #pragma unroll
        for (int nt = 0; nt < 8; nt++) {
            oc[nt][0] *= al_lo; oc[nt][1] *= al_lo;
            oc[nt][2] *= al_hi; oc[nt][3] *= al_hi;
        }
        __syncwarp();   // P is warp-private (rows w*16..w*16+15)

        // ---- O += P V : 8 kt x 8 nt ----
        #pragma unroll
        for (int kt = 0; kt < 8; kt++) {
            uint32_t pa[4];
            pa[0] = sP[rlo * SD + kt * 8 + l4];
            pa[1] = sP[rhi * SD + kt * 8 + l4];
            pa[2] = sP[rlo * SD + kt * 8 + l4 + 4];
            pa[3] = sP[rhi * SD + kt * 8 + l4 + 4];
            #pragma unroll
            for (int nt = 0; nt < 8; nt++) {
                uint32_t b0 = sV[(kt * 8 + l4) * SD + nt * 8 + g];
                uint32_t b1 = sV[(kt * 8 + 4 + l4) * SD + nt * 8 + g];
                mma8(oc[nt], pa, b0, b1);
            }
        }
    }

    // ---- epilogue ----
    float il_lo = 1.f / l_lo, il_hi = 1.f / l_hi;
    float* olo = g_attn + ((size_t)(n * L_SEQ + qb * 64 + rlo)) * DM + hd * DV;
    float* ohi = g_attn + ((size_t)(n * L_SEQ + qb * 64 + rhi)) * DM + hd * DV;
    #pragma unroll
    for (int nt = 0; nt < 8; nt++) {
        int col = nt * 8 + 2 * l4;
        *(float2*)(olo + col) = make_float2(oc[nt][0] * il_lo, oc[nt][1] * il_lo);
        *(float2*)(ohi + col) = make_float2(oc[nt][2] * il_hi, oc[nt][3] * il_hi);
    }
}

// ================= FC: out[4096,1024] = X W^T + b =================
// CTA 128x128 tile, 256 thr (8 warps, 2m x 4n), k-chunk 32.
#define FSD 36
#define FC_SMEM (2 * 128 * FSD * 4)   // 36864 B

__global__ __launch_bounds__(256, 2)
void fc_mma(const float* __restrict__ W, const float* __restrict__ B,
            float* __restrict__ out)
{
    extern __shared__ uint32_t fsm[];
    uint32_t* sX = fsm;
    uint32_t* sW = fsm + 128 * FSD;

    const int ot = blockIdx.x, mt0 = blockIdx.y;
    const int tid = threadIdx.x, wid = tid >> 5, lane = tid & 31;
    const int wm = wid & 1, wn = wid >> 1;
    const int g = lane >> 2, l4 = lane & 3;

    const float* xb = g_attn + (size_t)(mt0 * 128) * DM;
    const float* wb = W + (size_t)(ot * 128) * DM;

    float c[4][4][4];
    #pragma unroll
    for (int a = 0; a < 4; a++)
        #pragma unroll
        for (int b = 0; b < 4; b++)
            #pragma unroll
            for (int d = 0; d < 4; d++) c[a][b][d] = 0.f;

    for (int kb = 0; kb < DM / 32; kb++) {
        __syncthreads();
        #pragma unroll
        for (int j = 0; j < 4; j++) {
            int idx = tid + j * 256;             // 1024 float4 slots
            int r = idx >> 3, c4 = (idx & 7) << 2;
            sts4_tf(&sX[r * FSD + c4],
                    *(const float4*)(xb + (size_t)r * DM + kb * 32 + c4));
            sts4_tf(&sW[r * FSD + c4],
                    *(const float4*)(wb + (size_t)r * DM + kb * 32 + c4));
        }
        __syncthreads();

        #pragma unroll
        for (int kt = 0; kt < 4; kt++) {
            uint32_t bfr[4][2];
            #pragma unroll
            for (int nt = 0; nt < 4; nt++) {
                const uint32_t* wr = &sW[(wn * 32 + nt * 8 + g) * FSD + kt * 8 + l4];
                bfr[nt][0] = wr[0];
                bfr[nt][1] = wr[4];
            }
            #pragma unroll
            for (int mt = 0; mt < 4; mt++) {
                uint32_t a[4];
                int r0 = wm * 64 + mt * 16 + g;
                a[0] = sX[r0 * FSD + kt * 8 + l4];
                a[1] = sX[(r0 + 8) * FSD + kt * 8 + l4];
                a[2] = sX[r0 * FSD + kt * 8 + l4 + 4];
                a[3] = sX[(r0 + 8) * FSD + kt * 8 + l4 + 4];
                #pragma unroll
                for (int nt = 0; nt < 4; nt++)
                    mma8(c[mt][nt], a, bfr[nt][0], bfr[nt][1]);
            }
        }
    }

    const int rbase = mt0 * 128 + wm * 64;
    const int cbase = ot * 128 + wn * 32;
    #pragma unroll
    for (int mt = 0; mt < 4; mt++) {
        int rl = rbase + mt * 16 + g, rh = rl + 8;
        #pragma unroll
        for (int nt = 0; nt < 4; nt++) {
            int col = cbase + nt * 8 + 2 * l4;
            float2 bi = *(const float2*)(B + col);
            *(float2*)(out + (size_t)rl * DM + col) =
                make_float2(c[mt][nt][0] + bi.x, c[mt][nt][1] + bi.y);
            *(float2*)(out + (size_t)rh * DM + col) =
                make_float2(c[mt][nt][2] + bi.x, c[mt][nt][3] + bi.y);
        }
    }
}

extern "C" void kernel_launch(void* const* d_in, const int* in_sizes, int n_in,
                              void* d_out, int out_size)
{
    const float* q    = (const float*)d_in[0];
    const float* k    = (const float*)d_in[1];
    const float* v    = (const float*)d_in[2];
    const int*   mask = (const int*)  d_in[3];
    const float* fw   = (const float*)d_in[4];
    const float* fb   = (const float*)d_in[5];
    float* out = (float*)d_out;

    cudaFuncSetAttribute(attn_mma, cudaFuncAttributeMaxDynamicSharedMemorySize,
                         ATT_SMEM);

    dim3 g1(L_SEQ / 64, NH, 2);
    attn_mma<<<g1, 128, ATT_SMEM>>>(q, k, v, mask);

    dim3 g2(DM / 128, (2 * L_SEQ) / 128);
    fc_mma<<<g2, 256, FC_SMEM>>>(fw, fb, out);
}